// round 1
// baseline (speedup 1.0000x reference)
#include <cuda_runtime.h>

#define S_LEN   2048
#define HID     2048
#define NHEADS  32
#define KVHEADS 8
#define HDIM    64
#define KVW     (KVHEADS * HDIM)   // 512

// Scratch (allocation-free rule: __device__ globals)
__device__ float g_Q[S_LEN * HID];        // 16 MB
__device__ float g_K[S_LEN * KVW];        // 4 MB
__device__ float g_V[S_LEN * KVW];        // 4 MB
__device__ float g_A[S_LEN * HID];        // 16 MB  (attention output, pre-Wo)

// ---------------------------------------------------------------------------
// SGEMM: C[M,N] = A[M,K] @ B[K,N], row-major fp32. 128x128x16 tile, 256 thr,
// 8x8 per-thread micro-tile. Requires M%128==0, N%128==0, K%16==0 (holds here).
// ---------------------------------------------------------------------------
__global__ __launch_bounds__(256) void sgemm128(const float* __restrict__ A,
                                                const float* __restrict__ B,
                                                float* __restrict__ C,
                                                int M, int N, int K)
{
    __shared__ float As[16][128];   // transposed A tile: As[k][m]
    __shared__ float Bs[16][128];

    const int tid = threadIdx.x;
    const int m0 = blockIdx.y * 128;
    const int n0 = blockIdx.x * 128;
    const int tx = tid & 15;        // 0..15
    const int ty = tid >> 4;        // 0..15

    // A tile loaders: 128 rows x 16 cols = 512 float4; (row, c4) pairs
    const int ar  = tid >> 2;       // 0..63
    const int ac4 = tid & 3;        // float4 index within row (16 floats)
    // B tile loaders: 16 rows x 128 cols = 512 float4
    const int br  = tid >> 5;       // 0..7
    const int bc4 = tid & 31;

    float acc[8][8];
#pragma unroll
    for (int i = 0; i < 8; i++)
#pragma unroll
        for (int j = 0; j < 8; j++) acc[i][j] = 0.f;

    for (int k0 = 0; k0 < K; k0 += 16) {
#pragma unroll
        for (int h = 0; h < 2; h++) {
            int row = ar + h * 64;
            float4 v = *(const float4*)(A + (size_t)(m0 + row) * K + k0 + ac4 * 4);
            As[ac4 * 4 + 0][row] = v.x;
            As[ac4 * 4 + 1][row] = v.y;
            As[ac4 * 4 + 2][row] = v.z;
            As[ac4 * 4 + 3][row] = v.w;
        }
#pragma unroll
        for (int h = 0; h < 2; h++) {
            int row = br + h * 8;
            float4 v = *(const float4*)(B + (size_t)(k0 + row) * N + n0 + bc4 * 4);
            *(float4*)(&Bs[row][bc4 * 4]) = v;
        }
        __syncthreads();

#pragma unroll
        for (int kk = 0; kk < 16; kk++) {
            float a[8], b[8];
#pragma unroll
            for (int i = 0; i < 8; i++) a[i] = As[kk][ty * 8 + i];
#pragma unroll
            for (int j = 0; j < 8; j++) b[j] = Bs[kk][tx * 8 + j];
#pragma unroll
            for (int i = 0; i < 8; i++)
#pragma unroll
                for (int j = 0; j < 8; j++)
                    acc[i][j] += a[i] * b[j];
        }
        __syncthreads();
    }

#pragma unroll
    for (int i = 0; i < 8; i++) {
        int m = m0 + ty * 8 + i;
#pragma unroll
        for (int j = 0; j < 8; j += 4) {
            float4 v = make_float4(acc[i][j], acc[i][j + 1], acc[i][j + 2], acc[i][j + 3]);
            *(float4*)(C + (size_t)m * N + n0 + tx * 8 + j) = v;
        }
    }
}

// ---------------------------------------------------------------------------
// RoPE in-place on Q (heads 0..31) and K (heads 32..39).
// grid = (S, 40), block = 32. Thread i owns the (i, i+32) rotation pair.
// ---------------------------------------------------------------------------
__global__ void rope_kernel()
{
    int s = blockIdx.x;
    int h = blockIdx.y;
    int i = threadIdx.x;      // 0..31

    float* base = (h < NHEADS)
        ? (g_Q + (size_t)s * HID + h * HDIM)
        : (g_K + (size_t)s * KVW + (h - NHEADS) * HDIM);

    float x1 = base[i];
    float x2 = base[i + 32];
    // inv_freq = 10000^(-i/32)
    const float LN10000 = 9.210340371976184f;
    float inv = expf(-(float)i * (LN10000 / 32.0f));
    float ang = (float)s * inv;
    float c, sn;
    sincosf(ang, &sn, &c);
    base[i]      = x1 * c - x2 * sn;
    base[i + 32] = x2 * c + x1 * sn;
}

// ---------------------------------------------------------------------------
// Causal GQA flash attention (fp32, online softmax).
// grid = (S/32, NHEADS), block = 256 (8 warps). Each warp owns 4 q rows;
// lane l owns score columns {l, l+32} and output dims {l, l+32}.
// kv head = head % KVHEADS (jnp.tile semantics).
// ---------------------------------------------------------------------------
#define BQ 32
#define BK 64
__global__ __launch_bounds__(256) void attn_kernel()
{
    __shared__ float Qs[BQ][HDIM];        // 8 KB
    __shared__ float Ks[BK][HDIM + 1];    // padded: conflict-free Ks[l][d]
    __shared__ float Vs[BK][HDIM + 1];

    const int head = blockIdx.y;
    const int kvh  = head % KVHEADS;
    const int q0   = blockIdx.x * BQ;
    const int tid  = threadIdx.x;
    const int w    = tid >> 5;
    const int l    = tid & 31;

    // Load Q tile (32 x 64)
    for (int idx = tid; idx < BQ * (HDIM / 4); idx += 256) {
        int r = idx / (HDIM / 4);
        int c = idx % (HDIM / 4);
        *(float4*)&Qs[r][c * 4] =
            *(const float4*)(g_Q + (size_t)(q0 + r) * HID + head * HDIM + c * 4);
    }

    float m[4], lsum[4], acc0[4], acc1[4];
#pragma unroll
    for (int r = 0; r < 4; r++) { m[r] = -1e30f; lsum[r] = 0.f; acc0[r] = 0.f; acc1[r] = 0.f; }

    const int qrow0 = q0 + w * 4;
    const int T = (q0 + BQ - 1) / BK + 1;   // causal tile count for this block

    for (int t = 0; t < T; t++) {
        const int k0 = t * BK;
        __syncthreads();
        for (int idx = tid; idx < BK * (HDIM / 4); idx += 256) {
            int r = idx / (HDIM / 4);
            int c = idx % (HDIM / 4);
            const float* kp = g_K + (size_t)(k0 + r) * KVW + kvh * HDIM + c * 4;
            const float* vp = g_V + (size_t)(k0 + r) * KVW + kvh * HDIM + c * 4;
            float4 kv = *(const float4*)kp;
            float4 vv = *(const float4*)vp;
            Ks[r][c*4+0] = kv.x; Ks[r][c*4+1] = kv.y; Ks[r][c*4+2] = kv.z; Ks[r][c*4+3] = kv.w;
            Vs[r][c*4+0] = vv.x; Vs[r][c*4+1] = vv.y; Vs[r][c*4+2] = vv.z; Vs[r][c*4+3] = vv.w;
        }
        __syncthreads();

#pragma unroll
        for (int r = 0; r < 4; r++) {
            const int qg = qrow0 + r;
            float s0 = 0.f, s1 = 0.f;
#pragma unroll
            for (int d = 0; d < HDIM; d++) {
                float qv = Qs[w * 4 + r][d];
                s0 += qv * Ks[l][d];
                s1 += qv * Ks[l + 32][d];
            }
            s0 *= 0.125f;
            s1 *= 0.125f;
            if (k0 + l      > qg) s0 = -1e30f;
            if (k0 + l + 32 > qg) s1 = -1e30f;

            float tm = fmaxf(s0, s1);
#pragma unroll
            for (int off = 16; off > 0; off >>= 1)
                tm = fmaxf(tm, __shfl_xor_sync(0xffffffffu, tm, off));

            float mnew  = fmaxf(m[r], tm);
            float alpha = __expf(m[r] - mnew);
            float p0 = __expf(s0 - mnew);
            float p1 = __expf(s1 - mnew);

            float psum = p0 + p1;
#pragma unroll
            for (int off = 16; off > 0; off >>= 1)
                psum += __shfl_xor_sync(0xffffffffu, psum, off);

            lsum[r] = lsum[r] * alpha + psum;
            m[r] = mnew;
            acc0[r] *= alpha;
            acc1[r] *= alpha;

#pragma unroll
            for (int k = 0; k < 32; k++) {
                float pk = __shfl_sync(0xffffffffu, p0, k);
                acc0[r] += pk * Vs[k][l];
                acc1[r] += pk * Vs[k][l + 32];
            }
#pragma unroll
            for (int k = 0; k < 32; k++) {
                float pk = __shfl_sync(0xffffffffu, p1, k);
                acc0[r] += pk * Vs[k + 32][l];
                acc1[r] += pk * Vs[k + 32][l + 32];
            }
        }
    }

#pragma unroll
    for (int r = 0; r < 4; r++) {
        const int qg = qrow0 + r;
        float inv = 1.0f / lsum[r];
        g_A[(size_t)qg * HID + head * HDIM + l]      = acc0[r] * inv;
        g_A[(size_t)qg * HID + head * HDIM + l + 32] = acc1[r] * inv;
    }
}

// ---------------------------------------------------------------------------
extern "C" void kernel_launch(void* const* d_in, const int* in_sizes, int n_in,
                              void* d_out, int out_size)
{
    const float* hs = (const float*)d_in[0];   // (1, 2048, 2048)
    const float* Wq = (const float*)d_in[1];   // (2048, 32, 64)  == (2048, 2048)
    const float* Wk = (const float*)d_in[2];   // (2048, 8, 64)   == (2048, 512)
    const float* Wv = (const float*)d_in[3];   // (2048, 8, 64)
    const float* Wo = (const float*)d_in[4];   // (2048, 2048)
    // d_in[5] = attention_mask: pure causal, regenerated analytically
    float* out = (float*)d_out;                // (1, 2048, 2048)

    float *Q, *K, *V, *A;
    cudaGetSymbolAddress((void**)&Q, g_Q);
    cudaGetSymbolAddress((void**)&K, g_K);
    cudaGetSymbolAddress((void**)&V, g_V);
    cudaGetSymbolAddress((void**)&A, g_A);

    // QKV projections
    sgemm128<<<dim3(HID / 128, S_LEN / 128), 256>>>(hs, Wq, Q, S_LEN, HID, HID);
    sgemm128<<<dim3(KVW / 128, S_LEN / 128), 256>>>(hs, Wk, K, S_LEN, KVW, HID);
    sgemm128<<<dim3(KVW / 128, S_LEN / 128), 256>>>(hs, Wv, V, S_LEN, KVW, HID);

    // RoPE on Q (32 heads) + K (8 heads)
    rope_kernel<<<dim3(S_LEN, NHEADS + KVHEADS), 32>>>();

    // Causal GQA attention
    attn_kernel<<<dim3(S_LEN / BQ, NHEADS), 256>>>();

    // Output projection
    sgemm128<<<dim3(HID / 128, S_LEN / 128), 256>>>(A, Wo, out, S_LEN, HID, HID);
}

// round 3
// speedup vs baseline: 1.4150x; 1.4150x over previous
#include <cuda_runtime.h>
#include <cstdint>

#define S_LEN   2048
#define HID     2048
#define NHEADS  32
#define KVHEADS 8
#define HDIM    64
#define KVW     (KVHEADS * HDIM)   // 512

// ---------------- scratch (__device__ globals; no allocs allowed) ----------
__device__ float g_Q[S_LEN * HID];        // 16 MB
__device__ float g_K[S_LEN * KVW];        // 4 MB
__device__ float g_V[S_LEN * KVW];        // 4 MB
__device__ float g_A[S_LEN * HID];        // 16 MB
__device__ float g_WqT[HID * HID];        // [N,K] K-major, tf32-rounded
__device__ float g_WkT[KVW * HID];
__device__ float g_WvT[KVW * HID];
__device__ float g_WoT[HID * HID];

// ---------------- helpers ---------------------------------------------------
__device__ __forceinline__ uint32_t smem_u32(const void* p) {
    uint32_t a;
    asm("{ .reg .u64 t; cvta.to.shared.u64 t, %1; cvt.u32.u64 %0, t; }" : "=r"(a) : "l"(p));
    return a;
}
__device__ __forceinline__ float tf32r(float x) {       // returns rounded float
    uint32_t u;
    asm("cvt.rna.tf32.f32 %0, %1;" : "=r"(u) : "f"(x));
    return __uint_as_float(u);
}
__device__ __forceinline__ uint32_t tf32u(float x) {    // returns tf32 bits
    uint32_t u;
    asm("cvt.rna.tf32.f32 %0, %1;" : "=r"(u) : "f"(x));
    return u;
}
__device__ __forceinline__ void mma_tf32(float* d, const uint32_t* a, const uint32_t* b) {
    asm volatile("mma.sync.aligned.m16n8k8.row.col.f32.tf32.tf32.f32 "
        "{%0,%1,%2,%3}, {%4,%5,%6,%7}, {%8,%9}, {%0,%1,%2,%3};"
        : "+f"(d[0]), "+f"(d[1]), "+f"(d[2]), "+f"(d[3])
        : "r"(a[0]), "r"(a[1]), "r"(a[2]), "r"(a[3]), "r"(b[0]), "r"(b[1]));
}
#define CP_ASYNC16(dst, src) \
    asm volatile("cp.async.cg.shared.global [%0], [%1], 16;" :: "r"(dst), "l"(src) : "memory")
#define CP_COMMIT()  asm volatile("cp.async.commit_group;" ::: "memory")
#define CP_WAIT(n)   asm volatile("cp.async.wait_group %0;" :: "n"(n) : "memory")

// ---------------------------------------------------------------------------
// tf32 mma.sync GEMM: C[M,N] = A[M,K] @ Bt[N,K]^T, fp32 in/out.
// CTA 128x128, 8 warps (2M x 4N), warp tile 64x32, K-chunk 32, 2-stage cp.async.
// Bt must be pre-rounded to tf32; A rounded in-register.
// Requires M%128==0, N%128==0, K%32==0.
// ---------------------------------------------------------------------------
#define PAD 36
#define STAGE_FLOATS (2 * 128 * PAD)                 // A tile + B tile
#define GEMM_SMEM_BYTES (2 * STAGE_FLOATS * 4)       // two stages

__device__ __forceinline__ void gemm_issue_stage(const float* A, const float* Bt,
                                                 float* sm, int m0, int n0, int K,
                                                 int kc, int lrow, int lhalf)
{
    float* Ad = sm + (kc & 1) * STAGE_FLOATS;
    float* Bd = Ad + 128 * PAD;
    const float* Ap = A  + (size_t)(m0 + lrow) * K + kc * 32 + lhalf;
    const float* Bp = Bt + (size_t)(n0 + lrow) * K + kc * 32 + lhalf;
    uint32_t da = smem_u32(Ad + lrow * PAD + lhalf);
    uint32_t db = smem_u32(Bd + lrow * PAD + lhalf);
#pragma unroll
    for (int j = 0; j < 4; j++) {
        CP_ASYNC16(da + j * 16, Ap + j * 4);
        CP_ASYNC16(db + j * 16, Bp + j * 4);
    }
}

__global__ __launch_bounds__(256) void mma_gemm(const float* __restrict__ A,
                                                const float* __restrict__ Bt,
                                                float* __restrict__ C,
                                                int M, int N, int K)
{
    extern __shared__ float sm[];
    const int tid  = threadIdx.x;
    const int wid  = tid >> 5;
    const int lane = tid & 31;
    const int g = lane >> 2;          // 0..7
    const int q = lane & 3;           // 0..3
    const int m0 = blockIdx.y * 128;
    const int n0 = blockIdx.x * 128;
    const int wm = (wid & 1) * 64;    // warp M offset in tile
    const int wn = (wid >> 1) * 32;   // warp N offset in tile

    const int lrow  = tid >> 1;       // 0..127 (loader row)
    const int lhalf = (tid & 1) * 16; // float offset within 32-float row

    float acc[4][4][4];
#pragma unroll
    for (int i = 0; i < 4; i++)
#pragma unroll
        for (int j = 0; j < 4; j++)
#pragma unroll
            for (int k = 0; k < 4; k++) acc[i][j][k] = 0.f;

    const int nch = K / 32;
    gemm_issue_stage(A, Bt, sm, m0, n0, K, 0, lrow, lhalf);
    CP_COMMIT();

    for (int kc = 0; kc < nch; kc++) {
        if (kc + 1 < nch) {
            gemm_issue_stage(A, Bt, sm, m0, n0, K, kc + 1, lrow, lhalf);
            CP_COMMIT();
            CP_WAIT(1);
        } else {
            CP_WAIT(0);
        }
        __syncthreads();

        const float* Ab = sm + (kc & 1) * STAGE_FLOATS;
        const float* Bb = Ab + 128 * PAD;

#pragma unroll
        for (int ks = 0; ks < 4; ks++) {
            const int kk = ks * 8;
            uint32_t af[4][4];
#pragma unroll
            for (int fm = 0; fm < 4; fm++) {
                const float* ar = Ab + (wm + fm * 16 + g) * PAD + kk + q;
                af[fm][0] = tf32u(ar[0]);            // (g,   q)
                af[fm][2] = tf32u(ar[4]);            // (g,   q+4)
                af[fm][1] = tf32u(ar[8 * PAD]);      // (g+8, q)
                af[fm][3] = tf32u(ar[8 * PAD + 4]);  // (g+8, q+4)
            }
            uint32_t bf[4][2];
#pragma unroll
            for (int fn = 0; fn < 4; fn++) {
                const float* br = Bb + (wn + fn * 8 + g) * PAD + kk + q;
                bf[fn][0] = __float_as_uint(br[0]);  // B[k=q,   n=g]
                bf[fn][1] = __float_as_uint(br[4]);  // B[k=q+4, n=g]
            }
#pragma unroll
            for (int fm = 0; fm < 4; fm++)
#pragma unroll
                for (int fn = 0; fn < 4; fn++)
                    mma_tf32(acc[fm][fn], af[fm], bf[fn]);
        }
        __syncthreads();
    }

#pragma unroll
    for (int fm = 0; fm < 4; fm++) {
        const int r0 = m0 + wm + fm * 16 + g;
#pragma unroll
        for (int fn = 0; fn < 4; fn++) {
            const int c = n0 + wn + fn * 8 + 2 * q;
            *(float2*)(C + (size_t)r0 * N + c)       = make_float2(acc[fm][fn][0], acc[fm][fn][1]);
            *(float2*)(C + (size_t)(r0 + 8) * N + c) = make_float2(acc[fm][fn][2], acc[fm][fn][3]);
        }
    }
}

// ---------------------------------------------------------------------------
// Transpose + round-to-tf32: dst[C][R] = tf32(src[R][C])
// ---------------------------------------------------------------------------
__global__ void transpose_rnd(const float* __restrict__ src, float* __restrict__ dst,
                              int R, int C)
{
    __shared__ float t[32][33];
    const int bx = blockIdx.x * 32;
    const int by = blockIdx.y * 32;
    const int x = threadIdx.x, y = threadIdx.y;  // 32 x 8
#pragma unroll
    for (int i = 0; i < 32; i += 8)
        t[y + i][x] = src[(size_t)(by + y + i) * C + bx + x];
    __syncthreads();
#pragma unroll
    for (int i = 0; i < 32; i += 8)
        dst[(size_t)(bx + y + i) * R + by + x] = tf32r(t[x][y + i]);
}

// ---------------------------------------------------------------------------
// RoPE in-place on Q (heads 0..31) and K (heads 32..39).
// ---------------------------------------------------------------------------
__global__ void rope_kernel()
{
    int s = blockIdx.x;
    int h = blockIdx.y;
    int i = threadIdx.x;      // 0..31

    float* base = (h < NHEADS)
        ? (g_Q + (size_t)s * HID + h * HDIM)
        : (g_K + (size_t)s * KVW + (h - NHEADS) * HDIM);

    float x1 = base[i];
    float x2 = base[i + 32];
    const float LN10000 = 9.210340371976184f;
    float inv = expf(-(float)i * (LN10000 / 32.0f));
    float ang = (float)s * inv;
    float c, sn;
    sincosf(ang, &sn, &c);
    base[i]      = x1 * c - x2 * sn;
    base[i + 32] = x2 * c + x1 * sn;
}

// ---------------------------------------------------------------------------
// Causal GQA flash attention (fp32, online softmax).
// ---------------------------------------------------------------------------
#define BQ 32
#define BK 64
__global__ __launch_bounds__(256) void attn_kernel()
{
    __shared__ float Qs[BQ][HDIM];
    __shared__ float Ks[BK][HDIM + 1];
    __shared__ float Vs[BK][HDIM + 1];

    const int head = blockIdx.y;
    const int kvh  = head % KVHEADS;
    const int q0   = blockIdx.x * BQ;
    const int tid  = threadIdx.x;
    const int w    = tid >> 5;
    const int l    = tid & 31;

    for (int idx = tid; idx < BQ * (HDIM / 4); idx += 256) {
        int r = idx / (HDIM / 4);
        int c = idx % (HDIM / 4);
        *(float4*)&Qs[r][c * 4] =
            *(const float4*)(g_Q + (size_t)(q0 + r) * HID + head * HDIM + c * 4);
    }

    float m[4], lsum[4], acc0[4], acc1[4];
#pragma unroll
    for (int r = 0; r < 4; r++) { m[r] = -1e30f; lsum[r] = 0.f; acc0[r] = 0.f; acc1[r] = 0.f; }

    const int qrow0 = q0 + w * 4;
    const int T = (q0 + BQ - 1) / BK + 1;

    for (int t = 0; t < T; t++) {
        const int k0 = t * BK;
        __syncthreads();
        for (int idx = tid; idx < BK * (HDIM / 4); idx += 256) {
            int r = idx / (HDIM / 4);
            int c = idx % (HDIM / 4);
            const float* kp = g_K + (size_t)(k0 + r) * KVW + kvh * HDIM + c * 4;
            const float* vp = g_V + (size_t)(k0 + r) * KVW + kvh * HDIM + c * 4;
            float4 kv = *(const float4*)kp;
            float4 vv = *(const float4*)vp;
            Ks[r][c*4+0] = kv.x; Ks[r][c*4+1] = kv.y; Ks[r][c*4+2] = kv.z; Ks[r][c*4+3] = kv.w;
            Vs[r][c*4+0] = vv.x; Vs[r][c*4+1] = vv.y; Vs[r][c*4+2] = vv.z; Vs[r][c*4+3] = vv.w;
        }
        __syncthreads();

#pragma unroll
        for (int r = 0; r < 4; r++) {
            const int qg = qrow0 + r;
            float s0 = 0.f, s1 = 0.f;
#pragma unroll
            for (int d = 0; d < HDIM; d++) {
                float qv = Qs[w * 4 + r][d];
                s0 += qv * Ks[l][d];
                s1 += qv * Ks[l + 32][d];
            }
            s0 *= 0.125f;
            s1 *= 0.125f;
            if (k0 + l      > qg) s0 = -1e30f;
            if (k0 + l + 32 > qg) s1 = -1e30f;

            float tm = fmaxf(s0, s1);
#pragma unroll
            for (int off = 16; off > 0; off >>= 1)
                tm = fmaxf(tm, __shfl_xor_sync(0xffffffffu, tm, off));

            float mnew  = fmaxf(m[r], tm);
            float alpha = __expf(m[r] - mnew);
            float p0 = __expf(s0 - mnew);
            float p1 = __expf(s1 - mnew);

            float psum = p0 + p1;
#pragma unroll
            for (int off = 16; off > 0; off >>= 1)
                psum += __shfl_xor_sync(0xffffffffu, psum, off);

            lsum[r] = lsum[r] * alpha + psum;
            m[r] = mnew;
            acc0[r] *= alpha;
            acc1[r] *= alpha;

#pragma unroll
            for (int k = 0; k < 32; k++) {
                float pk = __shfl_sync(0xffffffffu, p0, k);
                acc0[r] += pk * Vs[k][l];
                acc1[r] += pk * Vs[k][l + 32];
            }
#pragma unroll
            for (int k = 0; k < 32; k++) {
                float pk = __shfl_sync(0xffffffffu, p1, k);
                acc0[r] += pk * Vs[k + 32][l];
                acc1[r] += pk * Vs[k + 32][l + 32];
            }
        }
    }

#pragma unroll
    for (int r = 0; r < 4; r++) {
        const int qg = qrow0 + r;
        float inv = 1.0f / lsum[r];
        g_A[(size_t)qg * HID + head * HDIM + l]      = acc0[r] * inv;
        g_A[(size_t)qg * HID + head * HDIM + l + 32] = acc1[r] * inv;
    }
}

// ---------------------------------------------------------------------------
extern "C" void kernel_launch(void* const* d_in, const int* in_sizes, int n_in,
                              void* d_out, int out_size)
{
    const float* hs = (const float*)d_in[0];   // (1, 2048, 2048)
    const float* Wq = (const float*)d_in[1];   // (2048, 2048)
    const float* Wk = (const float*)d_in[2];   // (2048, 512)
    const float* Wv = (const float*)d_in[3];   // (2048, 512)
    const float* Wo = (const float*)d_in[4];   // (2048, 2048)
    float* out = (float*)d_out;

    float *Q, *K, *V, *A, *WqT, *WkT, *WvT, *WoT;
    cudaGetSymbolAddress((void**)&Q, g_Q);
    cudaGetSymbolAddress((void**)&K, g_K);
    cudaGetSymbolAddress((void**)&V, g_V);
    cudaGetSymbolAddress((void**)&A, g_A);
    cudaGetSymbolAddress((void**)&WqT, g_WqT);
    cudaGetSymbolAddress((void**)&WkT, g_WkT);
    cudaGetSymbolAddress((void**)&WvT, g_WvT);
    cudaGetSymbolAddress((void**)&WoT, g_WoT);

    cudaFuncSetAttribute(mma_gemm, cudaFuncAttributeMaxDynamicSharedMemorySize,
                         GEMM_SMEM_BYTES);

    dim3 tb(32, 8);
    transpose_rnd<<<dim3(HID / 32, HID / 32), tb>>>(Wq, WqT, HID, HID);
    transpose_rnd<<<dim3(KVW / 32, HID / 32), tb>>>(Wk, WkT, HID, KVW);
    transpose_rnd<<<dim3(KVW / 32, HID / 32), tb>>>(Wv, WvT, HID, KVW);
    transpose_rnd<<<dim3(HID / 32, HID / 32), tb>>>(Wo, WoT, HID, HID);

    mma_gemm<<<dim3(HID / 128, S_LEN / 128), 256, GEMM_SMEM_BYTES>>>(hs, WqT, Q, S_LEN, HID, HID);
    mma_gemm<<<dim3(KVW / 128, S_LEN / 128), 256, GEMM_SMEM_BYTES>>>(hs, WkT, K, S_LEN, KVW, HID);
    mma_gemm<<<dim3(KVW / 128, S_LEN / 128), 256, GEMM_SMEM_BYTES>>>(hs, WvT, V, S_LEN, KVW, HID);

    rope_kernel<<<dim3(S_LEN, NHEADS + KVHEADS), 32>>>();

    attn_kernel<<<dim3(S_LEN / BQ, NHEADS), 256>>>();

    mma_gemm<<<dim3(HID / 128, S_LEN / 128), 256, GEMM_SMEM_BYTES>>>(A, WoT, out, S_LEN, HID, HID);
}

// round 4
// speedup vs baseline: 3.1923x; 2.2561x over previous
#include <cuda_runtime.h>
#include <cstdint>

#define S_LEN   2048
#define HID     2048
#define NHEADS  32
#define KVHEADS 8
#define HDIM    64
#define KVW     (KVHEADS * HDIM)   // 512

// ---------------- scratch (__device__ globals; no allocs allowed) ----------
__device__ float g_Q[S_LEN * HID];
__device__ float g_K[S_LEN * KVW];
__device__ float g_V[S_LEN * KVW];
__device__ float g_A[S_LEN * HID];
__device__ float g_HSr[S_LEN * HID];      // tf32-rounded hidden_states
__device__ float g_WqT[HID * HID];        // [N,K] K-major, tf32-rounded
__device__ float g_WkT[KVW * HID];
__device__ float g_WvT[KVW * HID];
__device__ float g_WoT[HID * HID];

// ---------------- helpers ---------------------------------------------------
__device__ __forceinline__ uint32_t smem_u32(const void* p) {
    uint32_t a;
    asm("{ .reg .u64 t; cvta.to.shared.u64 t, %1; cvt.u32.u64 %0, t; }" : "=r"(a) : "l"(p));
    return a;
}
__device__ __forceinline__ float tf32r(float x) {
    uint32_t u;
    asm("cvt.rna.tf32.f32 %0, %1;" : "=r"(u) : "f"(x));
    return __uint_as_float(u);
}
__device__ __forceinline__ uint32_t tf32u(float x) {
    uint32_t u;
    asm("cvt.rna.tf32.f32 %0, %1;" : "=r"(u) : "f"(x));
    return u;
}
__device__ __forceinline__ void mma_tf32(float* d, const uint32_t* a, const uint32_t* b) {
    asm volatile("mma.sync.aligned.m16n8k8.row.col.f32.tf32.tf32.f32 "
        "{%0,%1,%2,%3}, {%4,%5,%6,%7}, {%8,%9}, {%0,%1,%2,%3};"
        : "+f"(d[0]), "+f"(d[1]), "+f"(d[2]), "+f"(d[3])
        : "r"(a[0]), "r"(a[1]), "r"(a[2]), "r"(a[3]), "r"(b[0]), "r"(b[1]));
}
#define CP_ASYNC16(dst, src) \
    asm volatile("cp.async.cg.shared.global [%0], [%1], 16;" :: "r"(dst), "l"(src) : "memory")
#define CP_COMMIT()  asm volatile("cp.async.commit_group;" ::: "memory")
#define CP_WAIT(n)   asm volatile("cp.async.wait_group %0;" :: "n"(n) : "memory")

// ---------------------------------------------------------------------------
// tf32 mma.sync GEMM: C = A[M,K] @ Bt[N,K]^T. A and Bt must be PRE-ROUNDED tf32.
// CTA 128x128, 8 warps (2M x 4N), warp tile 64x32, K-chunk 32, 2-stage cp.async.
// ---------------------------------------------------------------------------
#define PAD 36
#define STAGE_FLOATS (2 * 128 * PAD)
#define GEMM_SMEM_BYTES (2 * STAGE_FLOATS * 4)

__device__ __forceinline__ void gemm_issue_stage(const float* A, const float* Bt,
                                                 float* sm, int m0, int n0, int K,
                                                 int kc, int lrow, int lhalf)
{
    float* Ad = sm + (kc & 1) * STAGE_FLOATS;
    float* Bd = Ad + 128 * PAD;
    const float* Ap = A  + (size_t)(m0 + lrow) * K + kc * 32 + lhalf;
    const float* Bp = Bt + (size_t)(n0 + lrow) * K + kc * 32 + lhalf;
    uint32_t da = smem_u32(Ad + lrow * PAD + lhalf);
    uint32_t db = smem_u32(Bd + lrow * PAD + lhalf);
#pragma unroll
    for (int j = 0; j < 4; j++) {
        CP_ASYNC16(da + j * 16, Ap + j * 4);
        CP_ASYNC16(db + j * 16, Bp + j * 4);
    }
}

__global__ __launch_bounds__(256) void mma_gemm(const float* __restrict__ A,
                                                const float* __restrict__ Bt,
                                                float* __restrict__ C,
                                                int M, int N, int K, int roundC)
{
    extern __shared__ float sm[];
    const int tid  = threadIdx.x;
    const int wid  = tid >> 5;
    const int lane = tid & 31;
    const int g = lane >> 2;
    const int q = lane & 3;
    const int m0 = blockIdx.y * 128;
    const int n0 = blockIdx.x * 128;
    const int wm = (wid & 1) * 64;
    const int wn = (wid >> 1) * 32;

    const int lrow  = tid >> 1;
    const int lhalf = (tid & 1) * 16;

    float acc[4][4][4];
#pragma unroll
    for (int i = 0; i < 4; i++)
#pragma unroll
        for (int j = 0; j < 4; j++)
#pragma unroll
            for (int k = 0; k < 4; k++) acc[i][j][k] = 0.f;

    const int nch = K / 32;
    gemm_issue_stage(A, Bt, sm, m0, n0, K, 0, lrow, lhalf);
    CP_COMMIT();

    for (int kc = 0; kc < nch; kc++) {
        if (kc + 1 < nch) {
            gemm_issue_stage(A, Bt, sm, m0, n0, K, kc + 1, lrow, lhalf);
            CP_COMMIT();
            CP_WAIT(1);
        } else {
            CP_WAIT(0);
        }
        __syncthreads();

        const float* Ab = sm + (kc & 1) * STAGE_FLOATS;
        const float* Bb = Ab + 128 * PAD;

#pragma unroll
        for (int ks = 0; ks < 4; ks++) {
            const int kk = ks * 8;
            uint32_t af[4][4];
#pragma unroll
            for (int fm = 0; fm < 4; fm++) {
                const float* ar = Ab + (wm + fm * 16 + g) * PAD + kk + q;
                af[fm][0] = __float_as_uint(ar[0]);
                af[fm][2] = __float_as_uint(ar[4]);
                af[fm][1] = __float_as_uint(ar[8 * PAD]);
                af[fm][3] = __float_as_uint(ar[8 * PAD + 4]);
            }
            uint32_t bf[4][2];
#pragma unroll
            for (int fn = 0; fn < 4; fn++) {
                const float* br = Bb + (wn + fn * 8 + g) * PAD + kk + q;
                bf[fn][0] = __float_as_uint(br[0]);
                bf[fn][1] = __float_as_uint(br[4]);
            }
#pragma unroll
            for (int fm = 0; fm < 4; fm++)
#pragma unroll
                for (int fn = 0; fn < 4; fn++)
                    mma_tf32(acc[fm][fn], af[fm], bf[fn]);
        }
        __syncthreads();
    }

#pragma unroll
    for (int fm = 0; fm < 4; fm++) {
        const int r0 = m0 + wm + fm * 16 + g;
#pragma unroll
        for (int fn = 0; fn < 4; fn++) {
            const int c = n0 + wn + fn * 8 + 2 * q;
            float2 v0 = make_float2(acc[fm][fn][0], acc[fm][fn][1]);
            float2 v1 = make_float2(acc[fm][fn][2], acc[fm][fn][3]);
            if (roundC) {
                v0.x = tf32r(v0.x); v0.y = tf32r(v0.y);
                v1.x = tf32r(v1.x); v1.y = tf32r(v1.y);
            }
            *(float2*)(C + (size_t)r0 * N + c)       = v0;
            *(float2*)(C + (size_t)(r0 + 8) * N + c) = v1;
        }
    }
}

// ---------------------------------------------------------------------------
// round_copy: dst = tf32(src), float4 grid-stride
// ---------------------------------------------------------------------------
__global__ void round_copy(const float* __restrict__ src, float* __restrict__ dst, int n)
{
    int i = (blockIdx.x * blockDim.x + threadIdx.x) * 4;
    if (i < n) {
        float4 v = *(const float4*)(src + i);
        v.x = tf32r(v.x); v.y = tf32r(v.y); v.z = tf32r(v.z); v.w = tf32r(v.w);
        *(float4*)(dst + i) = v;
    }
}

// ---------------------------------------------------------------------------
// Transpose + round-to-tf32: dst[C][R] = tf32(src[R][C])
// ---------------------------------------------------------------------------
__global__ void transpose_rnd(const float* __restrict__ src, float* __restrict__ dst,
                              int R, int C)
{
    __shared__ float t[32][33];
    const int bx = blockIdx.x * 32;
    const int by = blockIdx.y * 32;
    const int x = threadIdx.x, y = threadIdx.y;
#pragma unroll
    for (int i = 0; i < 32; i += 8)
        t[y + i][x] = src[(size_t)(by + y + i) * C + bx + x];
    __syncthreads();
#pragma unroll
    for (int i = 0; i < 32; i += 8)
        dst[(size_t)(bx + y + i) * R + by + x] = tf32r(t[x][y + i]);
}

// ---------------------------------------------------------------------------
// RoPE in-place. Q (heads 0..31): rotate, scale by 1/8, round to tf32.
// K (heads 32..39): rotate, round to tf32.
// ---------------------------------------------------------------------------
__global__ void rope_kernel()
{
    int s = blockIdx.x;
    int h = blockIdx.y;
    int i = threadIdx.x;      // 0..31

    const bool isQ = (h < NHEADS);
    float* base = isQ
        ? (g_Q + (size_t)s * HID + h * HDIM)
        : (g_K + (size_t)s * KVW + (h - NHEADS) * HDIM);
    const float scale = isQ ? 0.125f : 1.0f;

    float x1 = base[i];
    float x2 = base[i + 32];
    const float LN10000 = 9.210340371976184f;
    float inv = expf(-(float)i * (LN10000 / 32.0f));
    float ang = (float)s * inv;
    float c, sn;
    sincosf(ang, &sn, &c);
    base[i]      = tf32r((x1 * c - x2 * sn) * scale);
    base[i + 32] = tf32r((x2 * c + x1 * sn) * scale);
}

// ---------------------------------------------------------------------------
// Tensor-core causal GQA flash attention (tf32 mma, online softmax).
// CTA: 128 threads (4 warps), BQ=64 (warp = 16 q rows), BK=64.
// K/V double-buffered via cp.async. Q pre-scaled by 1/8 and tf32-rounded.
// grid = (NHEADS, S/64); qblock reversed so heaviest CTAs launch first.
// ---------------------------------------------------------------------------
#define AQ_PAD 68
#define AV_PAD 72
#define ATT_QF (64 * AQ_PAD)
#define ATT_KF (64 * AQ_PAD)
#define ATT_VF (64 * AV_PAD)
#define ATT_SMEM_BYTES ((ATT_QF + 2 * ATT_KF + 2 * ATT_VF) * 4)

__device__ __forceinline__ void attn_issue_kv(float* Kd, float* Vd,
                                              int k0, int kvh, int lr, int lc)
{
    const float* kg = g_K + (size_t)(k0 + lr) * KVW + kvh * HDIM + lc;
    const float* vg = g_V + (size_t)(k0 + lr) * KVW + kvh * HDIM + lc;
    uint32_t kd = smem_u32(Kd + lr * AQ_PAD + lc);
    uint32_t vd = smem_u32(Vd + lr * AV_PAD + lc);
#pragma unroll
    for (int j = 0; j < 8; j++) {
        CP_ASYNC16(kd + j * 16, kg + j * 4);
        CP_ASYNC16(vd + j * 16, vg + j * 4);
    }
}

__global__ __launch_bounds__(128) void attn_mma()
{
    extern __shared__ float sm[];
    float* Qs  = sm;
    float* Kb0 = sm + ATT_QF;
    float* Kb1 = Kb0 + ATT_KF;
    float* Vb0 = Kb1 + ATT_KF;
    float* Vb1 = Vb0 + ATT_VF;

    const int head = blockIdx.x;
    const int qb   = (gridDim.y - 1) - blockIdx.y;   // heavy CTAs first
    const int kvh  = head % KVHEADS;
    const int q0   = qb * 64;
    const int tid  = threadIdx.x;
    const int wid  = tid >> 5;
    const int lane = tid & 31;
    const int g = lane >> 2, q = lane & 3;
    const int wm = wid * 16;

    // Q tile (64 x 64) -> Qs (already tf32-rounded & pre-scaled)
    {
        const int r  = tid >> 1;
        const int f0 = (tid & 1) * 32;
        const float* src = g_Q + (size_t)(q0 + r) * HID + head * HDIM + f0;
        float* dst = Qs + r * AQ_PAD + f0;
#pragma unroll
        for (int j = 0; j < 8; j++)
            *(float4*)(dst + j * 4) = *(const float4*)(src + j * 4);
    }

    const int lr = tid >> 1;
    const int lc = (tid & 1) * 32;
    const int T = qb + 1;

    attn_issue_kv(Kb0, Vb0, 0, kvh, lr, lc);
    CP_COMMIT();

    __syncthreads();
    // Q fragments -> registers (held for whole kernel)
    uint32_t qf[8][4];
#pragma unroll
    for (int ks = 0; ks < 8; ks++) {
        const float* a = Qs + (wm + g) * AQ_PAD + ks * 8 + q;
        qf[ks][0] = __float_as_uint(a[0]);
        qf[ks][1] = __float_as_uint(a[8 * AQ_PAD]);
        qf[ks][2] = __float_as_uint(a[4]);
        qf[ks][3] = __float_as_uint(a[8 * AQ_PAD + 4]);
    }

    float o[8][4];
#pragma unroll
    for (int nf = 0; nf < 8; nf++)
#pragma unroll
        for (int j = 0; j < 4; j++) o[nf][j] = 0.f;
    float m0 = -1e30f, m1 = -1e30f, l0 = 0.f, l1 = 0.f;

    for (int t = 0; t < T; t++) {
        if (t + 1 < T) {
            attn_issue_kv(((t + 1) & 1) ? Kb1 : Kb0, ((t + 1) & 1) ? Vb1 : Vb0,
                          (t + 1) * 64, kvh, lr, lc);
            CP_COMMIT();
            CP_WAIT(1);
        } else {
            CP_WAIT(0);
        }
        __syncthreads();

        const float* Ks = (t & 1) ? Kb1 : Kb0;
        const float* Vs = (t & 1) ? Vb1 : Vb0;

        // ---- S = Q K^T (scaled) ----
        float s[8][4];
#pragma unroll
        for (int nf = 0; nf < 8; nf++)
#pragma unroll
            for (int j = 0; j < 4; j++) s[nf][j] = 0.f;

#pragma unroll
        for (int ks = 0; ks < 8; ks++) {
#pragma unroll
            for (int nf = 0; nf < 8; nf++) {
                uint32_t b[2];
                const float* kp = Ks + (nf * 8 + g) * AQ_PAD + ks * 8 + q;
                b[0] = __float_as_uint(kp[0]);
                b[1] = __float_as_uint(kp[4]);
                mma_tf32(s[nf], qf[ks], b);
            }
        }

        // ---- causal mask (diagonal tile only; k0 == q0 there) ----
        if (t == T - 1) {
            const int row0 = q0 + wm + g;
#pragma unroll
            for (int nf = 0; nf < 8; nf++) {
                const int c = q0 + nf * 8 + 2 * q;
                if (c     > row0)     s[nf][0] = -1e30f;
                if (c + 1 > row0)     s[nf][1] = -1e30f;
                if (c     > row0 + 8) s[nf][2] = -1e30f;
                if (c + 1 > row0 + 8) s[nf][3] = -1e30f;
            }
        }

        // ---- online softmax ----
        float mx0 = -1e30f, mx1 = -1e30f;
#pragma unroll
        for (int nf = 0; nf < 8; nf++) {
            mx0 = fmaxf(mx0, fmaxf(s[nf][0], s[nf][1]));
            mx1 = fmaxf(mx1, fmaxf(s[nf][2], s[nf][3]));
        }
        mx0 = fmaxf(mx0, __shfl_xor_sync(0xffffffffu, mx0, 1));
        mx0 = fmaxf(mx0, __shfl_xor_sync(0xffffffffu, mx0, 2));
        mx1 = fmaxf(mx1, __shfl_xor_sync(0xffffffffu, mx1, 1));
        mx1 = fmaxf(mx1, __shfl_xor_sync(0xffffffffu, mx1, 2));

        const float m0n = fmaxf(m0, mx0);
        const float m1n = fmaxf(m1, mx1);
        const float al0 = __expf(m0 - m0n);
        const float al1 = __expf(m1 - m1n);

        float rs0 = 0.f, rs1 = 0.f;
#pragma unroll
        for (int nf = 0; nf < 8; nf++) {
            s[nf][0] = __expf(s[nf][0] - m0n);
            s[nf][1] = __expf(s[nf][1] - m0n);
            s[nf][2] = __expf(s[nf][2] - m1n);
            s[nf][3] = __expf(s[nf][3] - m1n);
            rs0 += s[nf][0] + s[nf][1];
            rs1 += s[nf][2] + s[nf][3];
        }
        rs0 += __shfl_xor_sync(0xffffffffu, rs0, 1);
        rs0 += __shfl_xor_sync(0xffffffffu, rs0, 2);
        rs1 += __shfl_xor_sync(0xffffffffu, rs1, 1);
        rs1 += __shfl_xor_sync(0xffffffffu, rs1, 2);

        l0 = l0 * al0 + rs0;
        l1 = l1 * al1 + rs1;
        m0 = m0n; m1 = m1n;

#pragma unroll
        for (int nf = 0; nf < 8; nf++) {
            o[nf][0] *= al0; o[nf][1] *= al0;
            o[nf][2] *= al1; o[nf][3] *= al1;
        }

        // ---- O += P V : P accumulator frags -> A operand via quad shuffles ----
        const int L = g * 4 + (q >> 1);
        const bool odd = q & 1;
#pragma unroll
        for (int ks = 0; ks < 8; ks++) {
            float v0 = __shfl_sync(0xffffffffu, s[ks][0], L);
            float v1 = __shfl_sync(0xffffffffu, s[ks][1], L);
            float v2 = __shfl_sync(0xffffffffu, s[ks][2], L);
            float v3 = __shfl_sync(0xffffffffu, s[ks][3], L);
            float w0 = __shfl_sync(0xffffffffu, s[ks][0], L + 2);
            float w1 = __shfl_sync(0xffffffffu, s[ks][1], L + 2);
            float w2 = __shfl_sync(0xffffffffu, s[ks][2], L + 2);
            float w3 = __shfl_sync(0xffffffffu, s[ks][3], L + 2);
            uint32_t a[4];
            a[0] = tf32u(odd ? v1 : v0);   // P[g,    8ks+q]
            a[1] = tf32u(odd ? v3 : v2);   // P[g+8,  8ks+q]
            a[2] = tf32u(odd ? w1 : w0);   // P[g,    8ks+q+4]
            a[3] = tf32u(odd ? w3 : w2);   // P[g+8,  8ks+q+4]
#pragma unroll
            for (int nf = 0; nf < 8; nf++) {
                uint32_t b[2];
                const float* vp = Vs + (ks * 8 + q) * AV_PAD + nf * 8 + g;
                b[0] = __float_as_uint(vp[0]);
                b[1] = __float_as_uint(vp[4 * AV_PAD]);
                mma_tf32(o[nf], a, b);
            }
        }
        __syncthreads();
    }

    // ---- epilogue: normalize, round (feeds Wo GEMM), store ----
    const float inv0 = 1.f / l0;
    const float inv1 = 1.f / l1;
    const int row0 = q0 + wm + g;
#pragma unroll
    for (int nf = 0; nf < 8; nf++) {
        float* p0 = g_A + (size_t)row0 * HID + head * HDIM + nf * 8 + 2 * q;
        float* p1 = p0 + (size_t)8 * HID;
        *(float2*)p0 = make_float2(tf32r(o[nf][0] * inv0), tf32r(o[nf][1] * inv0));
        *(float2*)p1 = make_float2(tf32r(o[nf][2] * inv1), tf32r(o[nf][3] * inv1));
    }
}

// ---------------------------------------------------------------------------
extern "C" void kernel_launch(void* const* d_in, const int* in_sizes, int n_in,
                              void* d_out, int out_size)
{
    const float* hs = (const float*)d_in[0];
    const float* Wq = (const float*)d_in[1];
    const float* Wk = (const float*)d_in[2];
    const float* Wv = (const float*)d_in[3];
    const float* Wo = (const float*)d_in[4];
    float* out = (float*)d_out;

    float *Q, *K, *V, *A, *HSr, *WqT, *WkT, *WvT, *WoT;
    cudaGetSymbolAddress((void**)&Q, g_Q);
    cudaGetSymbolAddress((void**)&K, g_K);
    cudaGetSymbolAddress((void**)&V, g_V);
    cudaGetSymbolAddress((void**)&A, g_A);
    cudaGetSymbolAddress((void**)&HSr, g_HSr);
    cudaGetSymbolAddress((void**)&WqT, g_WqT);
    cudaGetSymbolAddress((void**)&WkT, g_WkT);
    cudaGetSymbolAddress((void**)&WvT, g_WvT);
    cudaGetSymbolAddress((void**)&WoT, g_WoT);

    cudaFuncSetAttribute(mma_gemm, cudaFuncAttributeMaxDynamicSharedMemorySize,
                         GEMM_SMEM_BYTES);
    cudaFuncSetAttribute(attn_mma, cudaFuncAttributeMaxDynamicSharedMemorySize,
                         ATT_SMEM_BYTES);

    // Pre-rounded operands
    round_copy<<<(S_LEN * HID / 4 + 255) / 256, 256>>>(hs, HSr, S_LEN * HID);
    dim3 tb(32, 8);
    transpose_rnd<<<dim3(HID / 32, HID / 32), tb>>>(Wq, WqT, HID, HID);
    transpose_rnd<<<dim3(KVW / 32, HID / 32), tb>>>(Wk, WkT, HID, KVW);
    transpose_rnd<<<dim3(KVW / 32, HID / 32), tb>>>(Wv, WvT, HID, KVW);
    transpose_rnd<<<dim3(HID / 32, HID / 32), tb>>>(Wo, WoT, HID, HID);

    // Projections (V output rounded for the attention tf32 path)
    mma_gemm<<<dim3(HID / 128, S_LEN / 128), 256, GEMM_SMEM_BYTES>>>(HSr, WqT, Q, S_LEN, HID, HID, 0);
    mma_gemm<<<dim3(KVW / 128, S_LEN / 128), 256, GEMM_SMEM_BYTES>>>(HSr, WkT, K, S_LEN, KVW, HID, 0);
    mma_gemm<<<dim3(KVW / 128, S_LEN / 128), 256, GEMM_SMEM_BYTES>>>(HSr, WvT, V, S_LEN, KVW, HID, 1);

    // RoPE (rounds Q*0.125 and K to tf32)
    rope_kernel<<<dim3(S_LEN, NHEADS + KVHEADS), 32>>>();

    // Tensor-core causal attention
    attn_mma<<<dim3(NHEADS, S_LEN / 64), 128, ATT_SMEM_BYTES>>>();

    // Output projection (full fp32 output)
    mma_gemm<<<dim3(HID / 128, S_LEN / 128), 256, GEMM_SMEM_BYTES>>>(A, WoT, out, S_LEN, HID, HID, 0);
}

// round 5
// speedup vs baseline: 4.2032x; 1.3167x over previous
#include <cuda_runtime.h>
#include <cstdint>

#define S_LEN   2048
#define HID     2048
#define NHEADS  32
#define KVHEADS 8
#define HDIM    64
#define KVW     (KVHEADS * HDIM)   // 512
#define QKVW    (HID + 2 * KVW)    // 3072

// ---------------- scratch (__device__ globals; no allocs allowed) ----------
__device__ float g_QKV[S_LEN * QKVW];     // 24 MB: Q | K | V columns
__device__ float g_A[S_LEN * HID];        // 16 MB
__device__ float g_HSr[S_LEN * HID];      // tf32-rounded hidden_states
__device__ float g_WT[QKVW * HID];        // 24 MB: WqT | WkT | WvT, [N,K] tf32
__device__ float g_WoT[HID * HID];

// ---------------- helpers ---------------------------------------------------
__device__ __forceinline__ uint32_t smem_u32(const void* p) {
    uint32_t a;
    asm("{ .reg .u64 t; cvta.to.shared.u64 t, %1; cvt.u32.u64 %0, t; }" : "=r"(a) : "l"(p));
    return a;
}
__device__ __forceinline__ float tf32r(float x) {
    uint32_t u;
    asm("cvt.rna.tf32.f32 %0, %1;" : "=r"(u) : "f"(x));
    return __uint_as_float(u);
}
__device__ __forceinline__ uint32_t tf32u(float x) {
    uint32_t u;
    asm("cvt.rna.tf32.f32 %0, %1;" : "=r"(u) : "f"(x));
    return u;
}
__device__ __forceinline__ void mma_tf32(float* d, const uint32_t* a, const uint32_t* b) {
    asm volatile("mma.sync.aligned.m16n8k8.row.col.f32.tf32.tf32.f32 "
        "{%0,%1,%2,%3}, {%4,%5,%6,%7}, {%8,%9}, {%0,%1,%2,%3};"
        : "+f"(d[0]), "+f"(d[1]), "+f"(d[2]), "+f"(d[3])
        : "r"(a[0]), "r"(a[1]), "r"(a[2]), "r"(a[3]), "r"(b[0]), "r"(b[1]));
}
#define CP_ASYNC16(dst, src) \
    asm volatile("cp.async.cg.shared.global [%0], [%1], 16;" :: "r"(dst), "l"(src) : "memory")
#define CP_COMMIT()  asm volatile("cp.async.commit_group;" ::: "memory")
#define CP_WAIT(n)   asm volatile("cp.async.wait_group %0;" :: "n"(n) : "memory")

// ---------------------------------------------------------------------------
// tf32 mma.sync GEMM: C = A[M,K] @ Bt[N,K]^T. Operands PRE-ROUNDED tf32.
// CTA 128x128, 8 warps (2M x 4N), warp tile 64x32, K-chunk 32, 2-stage cp.async.
// Columns >= roundFrom get tf32-rounded on store (tile-uniform: roundFrom%128==0).
// ---------------------------------------------------------------------------
#define PAD 36
#define STAGE_FLOATS (2 * 128 * PAD)
#define GEMM_SMEM_BYTES (2 * STAGE_FLOATS * 4)

__device__ __forceinline__ void gemm_issue_stage(const float* A, const float* Bt,
                                                 float* sm, int m0, int n0, int K,
                                                 int kc, int lrow, int lhalf)
{
    float* Ad = sm + (kc & 1) * STAGE_FLOATS;
    float* Bd = Ad + 128 * PAD;
    const float* Ap = A  + (size_t)(m0 + lrow) * K + kc * 32 + lhalf;
    const float* Bp = Bt + (size_t)(n0 + lrow) * K + kc * 32 + lhalf;
    uint32_t da = smem_u32(Ad + lrow * PAD + lhalf);
    uint32_t db = smem_u32(Bd + lrow * PAD + lhalf);
#pragma unroll
    for (int j = 0; j < 4; j++) {
        CP_ASYNC16(da + j * 16, Ap + j * 4);
        CP_ASYNC16(db + j * 16, Bp + j * 4);
    }
}

__global__ __launch_bounds__(256) void mma_gemm(const float* __restrict__ A,
                                                const float* __restrict__ Bt,
                                                float* __restrict__ C,
                                                int M, int N, int K, int roundFrom)
{
    extern __shared__ float sm[];
    const int tid  = threadIdx.x;
    const int wid  = tid >> 5;
    const int lane = tid & 31;
    const int g = lane >> 2;
    const int q = lane & 3;
    const int m0 = blockIdx.y * 128;
    const int n0 = blockIdx.x * 128;
    const int wm = (wid & 1) * 64;
    const int wn = (wid >> 1) * 32;

    const int lrow  = tid >> 1;
    const int lhalf = (tid & 1) * 16;

    float acc[4][4][4];
#pragma unroll
    for (int i = 0; i < 4; i++)
#pragma unroll
        for (int j = 0; j < 4; j++)
#pragma unroll
            for (int k = 0; k < 4; k++) acc[i][j][k] = 0.f;

    const int nch = K / 32;
    gemm_issue_stage(A, Bt, sm, m0, n0, K, 0, lrow, lhalf);
    CP_COMMIT();

    for (int kc = 0; kc < nch; kc++) {
        if (kc + 1 < nch) {
            gemm_issue_stage(A, Bt, sm, m0, n0, K, kc + 1, lrow, lhalf);
            CP_COMMIT();
            CP_WAIT(1);
        } else {
            CP_WAIT(0);
        }
        __syncthreads();

        const float* Ab = sm + (kc & 1) * STAGE_FLOATS;
        const float* Bb = Ab + 128 * PAD;

#pragma unroll
        for (int ks = 0; ks < 4; ks++) {
            const int kk = ks * 8;
            uint32_t af[4][4];
#pragma unroll
            for (int fm = 0; fm < 4; fm++) {
                const float* ar = Ab + (wm + fm * 16 + g) * PAD + kk + q;
                af[fm][0] = __float_as_uint(ar[0]);
                af[fm][2] = __float_as_uint(ar[4]);
                af[fm][1] = __float_as_uint(ar[8 * PAD]);
                af[fm][3] = __float_as_uint(ar[8 * PAD + 4]);
            }
            uint32_t bf[4][2];
#pragma unroll
            for (int fn = 0; fn < 4; fn++) {
                const float* br = Bb + (wn + fn * 8 + g) * PAD + kk + q;
                bf[fn][0] = __float_as_uint(br[0]);
                bf[fn][1] = __float_as_uint(br[4]);
            }
#pragma unroll
            for (int fm = 0; fm < 4; fm++)
#pragma unroll
                for (int fn = 0; fn < 4; fn++)
                    mma_tf32(acc[fm][fn], af[fm], bf[fn]);
        }
        __syncthreads();
    }

    const bool rnd = (n0 >= roundFrom);
#pragma unroll
    for (int fm = 0; fm < 4; fm++) {
        const int r0 = m0 + wm + fm * 16 + g;
#pragma unroll
        for (int fn = 0; fn < 4; fn++) {
            const int c = n0 + wn + fn * 8 + 2 * q;
            float2 v0 = make_float2(acc[fm][fn][0], acc[fm][fn][1]);
            float2 v1 = make_float2(acc[fm][fn][2], acc[fm][fn][3]);
            if (rnd) {
                v0.x = tf32r(v0.x); v0.y = tf32r(v0.y);
                v1.x = tf32r(v1.x); v1.y = tf32r(v1.y);
            }
            *(float2*)(C + (size_t)r0 * N + c)       = v0;
            *(float2*)(C + (size_t)(r0 + 8) * N + c) = v1;
        }
    }
}

// ---------------------------------------------------------------------------
// round_copy: dst = tf32(src), float4
// ---------------------------------------------------------------------------
__global__ void round_copy(const float* __restrict__ src, float* __restrict__ dst, int n)
{
    int i = (blockIdx.x * blockDim.x + threadIdx.x) * 4;
    if (i < n) {
        float4 v = *(const float4*)(src + i);
        v.x = tf32r(v.x); v.y = tf32r(v.y); v.z = tf32r(v.z); v.w = tf32r(v.w);
        *(float4*)(dst + i) = v;
    }
}

// ---------------------------------------------------------------------------
// Transpose + round-to-tf32: dst[C][R] = tf32(src[R][C])
// ---------------------------------------------------------------------------
__global__ void transpose_rnd(const float* __restrict__ src, float* __restrict__ dst,
                              int R, int C)
{
    __shared__ float t[32][33];
    const int bx = blockIdx.x * 32;
    const int by = blockIdx.y * 32;
    const int x = threadIdx.x, y = threadIdx.y;
#pragma unroll
    for (int i = 0; i < 32; i += 8)
        t[y + i][x] = src[(size_t)(by + y + i) * C + bx + x];
    __syncthreads();
#pragma unroll
    for (int i = 0; i < 32; i += 8)
        dst[(size_t)(bx + y + i) * R + by + x] = tf32r(t[x][y + i]);
}

// ---------------------------------------------------------------------------
// RoPE in-place on g_QKV. Q (heads 0..31): rotate, *1/8, round.
// K (heads 32..39): rotate, round. 256 threads = 8 warps, one head each.
// grid = (S, 5).
// ---------------------------------------------------------------------------
__global__ __launch_bounds__(256) void rope_kernel()
{
    const int s = blockIdx.x;
    const int w = threadIdx.x >> 5;
    const int i = threadIdx.x & 31;
    const int h = blockIdx.y * 8 + w;      // 0..39

    const bool isQ = (h < NHEADS);
    float* base = isQ
        ? (g_QKV + (size_t)s * QKVW + h * HDIM)
        : (g_QKV + (size_t)s * QKVW + HID + (h - NHEADS) * HDIM);
    const float scale = isQ ? 0.125f : 1.0f;

    float x1 = base[i];
    float x2 = base[i + 32];
    const float LN10000 = 9.210340371976184f;
    float inv = expf(-(float)i * (LN10000 / 32.0f));
    float ang = (float)s * inv;
    float c, sn;
    sincosf(ang, &sn, &c);
    base[i]      = tf32r((x1 * c - x2 * sn) * scale);
    base[i + 32] = tf32r((x2 * c + x1 * sn) * scale);
}

// ---------------------------------------------------------------------------
// Tensor-core causal GQA flash attention (tf32 mma, online softmax).
// CTA: 256 threads (8 warps), BQ=128 (warp = 16 q rows), BK=64.
// Fully-masked (k0 beyond all warp rows) tiles skipped per-warp.
// grid = (NHEADS, S/128), qblock reversed so heaviest CTAs launch first.
// ---------------------------------------------------------------------------
#define AQ_PAD 68
#define AV_PAD 72
#define ATT_QF (128 * AQ_PAD)
#define ATT_KF (64 * AQ_PAD)
#define ATT_VF (64 * AV_PAD)
#define ATT_SMEM_BYTES ((ATT_QF + 2 * ATT_KF + 2 * ATT_VF) * 4)

__device__ __forceinline__ void attn_issue_kv(float* Kd, float* Vd,
                                              int k0, int kvh, int lr, int lc)
{
    const float* kg = g_QKV + (size_t)(k0 + lr) * QKVW + HID + kvh * HDIM + lc;
    const float* vg = kg + KVW;
    uint32_t kd = smem_u32(Kd + lr * AQ_PAD + lc);
    uint32_t vd = smem_u32(Vd + lr * AV_PAD + lc);
#pragma unroll
    for (int j = 0; j < 4; j++) {
        CP_ASYNC16(kd + j * 16, kg + j * 4);
        CP_ASYNC16(vd + j * 16, vg + j * 4);
    }
}

__global__ __launch_bounds__(256) void attn_mma()
{
    extern __shared__ float sm[];
    float* Qs  = sm;
    float* Kb0 = sm + ATT_QF;
    float* Kb1 = Kb0 + ATT_KF;
    float* Vb0 = Kb1 + ATT_KF;
    float* Vb1 = Vb0 + ATT_VF;

    const int head = blockIdx.x;
    const int qb   = (gridDim.y - 1) - blockIdx.y;   // heavy CTAs first
    const int kvh  = head % KVHEADS;
    const int q0   = qb * 128;
    const int tid  = threadIdx.x;
    const int wid  = tid >> 5;
    const int lane = tid & 31;
    const int g = lane >> 2, q = lane & 3;
    const int wm = wid * 16;

    // Q tile (128 x 64) -> Qs (tf32-rounded & pre-scaled by rope)
    {
        const int r  = tid >> 1;
        const int f0 = (tid & 1) * 32;
        const float* src = g_QKV + (size_t)(q0 + r) * QKVW + head * HDIM + f0;
        float* dst = Qs + r * AQ_PAD + f0;
#pragma unroll
        for (int j = 0; j < 8; j++)
            *(float4*)(dst + j * 4) = *(const float4*)(src + j * 4);
    }

    const int lr = tid >> 2;          // 0..63
    const int lc = (tid & 3) * 16;    // 0,16,32,48
    const int T = 2 * qb + 2;

    attn_issue_kv(Kb0, Vb0, 0, kvh, lr, lc);
    CP_COMMIT();

    __syncthreads();
    uint32_t qf[8][4];
#pragma unroll
    for (int ks = 0; ks < 8; ks++) {
        const float* a = Qs + (wm + g) * AQ_PAD + ks * 8 + q;
        qf[ks][0] = __float_as_uint(a[0]);
        qf[ks][1] = __float_as_uint(a[8 * AQ_PAD]);
        qf[ks][2] = __float_as_uint(a[4]);
        qf[ks][3] = __float_as_uint(a[8 * AQ_PAD + 4]);
    }

    float o[8][4];
#pragma unroll
    for (int nf = 0; nf < 8; nf++)
#pragma unroll
        for (int j = 0; j < 4; j++) o[nf][j] = 0.f;
    float m0 = -1e30f, m1 = -1e30f, l0 = 0.f, l1 = 0.f;

    for (int t = 0; t < T; t++) {
        if (t + 1 < T) {
            attn_issue_kv(((t + 1) & 1) ? Kb1 : Kb0, ((t + 1) & 1) ? Vb1 : Vb0,
                          (t + 1) * 64, kvh, lr, lc);
            CP_COMMIT();
            CP_WAIT(1);
        } else {
            CP_WAIT(0);
        }
        __syncthreads();

        const int k0 = t * 64;
        const bool active = (k0 <= q0 + wm + 15);   // warp-uniform

        if (active) {
            const float* Ks = (t & 1) ? Kb1 : Kb0;
            const float* Vs = (t & 1) ? Vb1 : Vb0;

            // ---- S = Q K^T ----
            float s[8][4];
#pragma unroll
            for (int nf = 0; nf < 8; nf++)
#pragma unroll
                for (int j = 0; j < 4; j++) s[nf][j] = 0.f;

#pragma unroll
            for (int ks = 0; ks < 8; ks++) {
#pragma unroll
                for (int nf = 0; nf < 8; nf++) {
                    uint32_t b[2];
                    const float* kp = Ks + (nf * 8 + g) * AQ_PAD + ks * 8 + q;
                    b[0] = __float_as_uint(kp[0]);
                    b[1] = __float_as_uint(kp[4]);
                    mma_tf32(s[nf], qf[ks], b);
                }
            }

            // ---- causal mask (only tiles overlapping the diagonal) ----
            if (k0 + 63 > q0 + wm) {
                const int row0 = q0 + wm + g;
#pragma unroll
                for (int nf = 0; nf < 8; nf++) {
                    const int c = k0 + nf * 8 + 2 * q;
                    if (c     > row0)     s[nf][0] = -1e30f;
                    if (c + 1 > row0)     s[nf][1] = -1e30f;
                    if (c     > row0 + 8) s[nf][2] = -1e30f;
                    if (c + 1 > row0 + 8) s[nf][3] = -1e30f;
                }
            }

            // ---- online softmax ----
            float mx0 = -1e30f, mx1 = -1e30f;
#pragma unroll
            for (int nf = 0; nf < 8; nf++) {
                mx0 = fmaxf(mx0, fmaxf(s[nf][0], s[nf][1]));
                mx1 = fmaxf(mx1, fmaxf(s[nf][2], s[nf][3]));
            }
            mx0 = fmaxf(mx0, __shfl_xor_sync(0xffffffffu, mx0, 1));
            mx0 = fmaxf(mx0, __shfl_xor_sync(0xffffffffu, mx0, 2));
            mx1 = fmaxf(mx1, __shfl_xor_sync(0xffffffffu, mx1, 1));
            mx1 = fmaxf(mx1, __shfl_xor_sync(0xffffffffu, mx1, 2));

            const float m0n = fmaxf(m0, mx0);
            const float m1n = fmaxf(m1, mx1);
            const float al0 = __expf(m0 - m0n);
            const float al1 = __expf(m1 - m1n);

            float rs0 = 0.f, rs1 = 0.f;
#pragma unroll
            for (int nf = 0; nf < 8; nf++) {
                s[nf][0] = __expf(s[nf][0] - m0n);
                s[nf][1] = __expf(s[nf][1] - m0n);
                s[nf][2] = __expf(s[nf][2] - m1n);
                s[nf][3] = __expf(s[nf][3] - m1n);
                rs0 += s[nf][0] + s[nf][1];
                rs1 += s[nf][2] + s[nf][3];
            }
            rs0 += __shfl_xor_sync(0xffffffffu, rs0, 1);
            rs0 += __shfl_xor_sync(0xffffffffu, rs0, 2);
            rs1 += __shfl_xor_sync(0xffffffffu, rs1, 1);
            rs1 += __shfl_xor_sync(0xffffffffu, rs1, 2);

            l0 = l0 * al0 + rs0;
            l1 = l1 * al1 + rs1;
            m0 = m0n; m1 = m1n;

#pragma unroll
            for (int nf = 0; nf < 8; nf++) {
                o[nf][0] *= al0; o[nf][1] *= al0;
                o[nf][2] *= al1; o[nf][3] *= al1;
            }

            // ---- O += P V ----
            const int L = g * 4 + (q >> 1);
            const bool odd = q & 1;
#pragma unroll
            for (int ks = 0; ks < 8; ks++) {
                float v0 = __shfl_sync(0xffffffffu, s[ks][0], L);
                float v1 = __shfl_sync(0xffffffffu, s[ks][1], L);
                float v2 = __shfl_sync(0xffffffffu, s[ks][2], L);
                float v3 = __shfl_sync(0xffffffffu, s[ks][3], L);
                float w0 = __shfl_sync(0xffffffffu, s[ks][0], L + 2);
                float w1 = __shfl_sync(0xffffffffu, s[ks][1], L + 2);
                float w2 = __shfl_sync(0xffffffffu, s[ks][2], L + 2);
                float w3 = __shfl_sync(0xffffffffu, s[ks][3], L + 2);
                uint32_t a[4];
                a[0] = tf32u(odd ? v1 : v0);
                a[1] = tf32u(odd ? v3 : v2);
                a[2] = tf32u(odd ? w1 : w0);
                a[3] = tf32u(odd ? w3 : w2);
#pragma unroll
                for (int nf = 0; nf < 8; nf++) {
                    uint32_t b[2];
                    const float* vp = Vs + (ks * 8 + q) * AV_PAD + nf * 8 + g;
                    b[0] = __float_as_uint(vp[0]);
                    b[1] = __float_as_uint(vp[4 * AV_PAD]);
                    mma_tf32(o[nf], a, b);
                }
            }
        }
        __syncthreads();
    }

    // ---- epilogue: normalize, round (feeds Wo GEMM), store ----
    const float inv0 = 1.f / l0;
    const float inv1 = 1.f / l1;
    const int row0 = q0 + wm + g;
#pragma unroll
    for (int nf = 0; nf < 8; nf++) {
        float* p0 = g_A + (size_t)row0 * HID + head * HDIM + nf * 8 + 2 * q;
        float* p1 = p0 + (size_t)8 * HID;
        *(float2*)p0 = make_float2(tf32r(o[nf][0] * inv0), tf32r(o[nf][1] * inv0));
        *(float2*)p1 = make_float2(tf32r(o[nf][2] * inv1), tf32r(o[nf][3] * inv1));
    }
}

// ---------------------------------------------------------------------------
extern "C" void kernel_launch(void* const* d_in, const int* in_sizes, int n_in,
                              void* d_out, int out_size)
{
    const float* hs = (const float*)d_in[0];
    const float* Wq = (const float*)d_in[1];
    const float* Wk = (const float*)d_in[2];
    const float* Wv = (const float*)d_in[3];
    const float* Wo = (const float*)d_in[4];
    float* out = (float*)d_out;

    float *QKV, *A, *HSr, *WT, *WoT;
    cudaGetSymbolAddress((void**)&QKV, g_QKV);
    cudaGetSymbolAddress((void**)&A, g_A);
    cudaGetSymbolAddress((void**)&HSr, g_HSr);
    cudaGetSymbolAddress((void**)&WT, g_WT);
    cudaGetSymbolAddress((void**)&WoT, g_WoT);

    cudaFuncSetAttribute(mma_gemm, cudaFuncAttributeMaxDynamicSharedMemorySize,
                         GEMM_SMEM_BYTES);
    cudaFuncSetAttribute(attn_mma, cudaFuncAttributeMaxDynamicSharedMemorySize,
                         ATT_SMEM_BYTES);

    // Pre-rounded operands; fused weight matrix [Wq|Wk|Wv]^T
    round_copy<<<(S_LEN * HID / 4 + 255) / 256, 256>>>(hs, HSr, S_LEN * HID);
    dim3 tb(32, 8);
    transpose_rnd<<<dim3(HID / 32, HID / 32), tb>>>(Wq, WT, HID, HID);
    transpose_rnd<<<dim3(KVW / 32, HID / 32), tb>>>(Wk, WT + (size_t)HID * HID, HID, KVW);
    transpose_rnd<<<dim3(KVW / 32, HID / 32), tb>>>(Wv, WT + (size_t)(HID + KVW) * HID, HID, KVW);
    transpose_rnd<<<dim3(HID / 32, HID / 32), tb>>>(Wo, WoT, HID, HID);

    // Fused QKV projection (V columns rounded for the tf32 PV path)
    mma_gemm<<<dim3(QKVW / 128, S_LEN / 128), 256, GEMM_SMEM_BYTES>>>(
        HSr, WT, QKV, S_LEN, QKVW, HID, HID + KVW);

    // RoPE (rounds Q*0.125 and K to tf32)
    rope_kernel<<<dim3(S_LEN, 5), 256>>>();

    // Tensor-core causal attention (BQ=128)
    attn_mma<<<dim3(NHEADS, S_LEN / 128), 256, ATT_SMEM_BYTES>>>();

    // Output projection
    mma_gemm<<<dim3(HID / 128, S_LEN / 128), 256, GEMM_SMEM_BYTES>>>(
        A, WoT, out, S_LEN, HID, HID, 1 << 30);
}